// round 15
// baseline (speedup 1.0000x reference)
#include <cuda_runtime.h>
#include <cuda_bf16.h>
#include <math.h>
#include <stdint.h>

// Problem constants
#define Bx    64
#define Tt    2048
#define HIDx  1024
#define ENCx  512
#define Ux    256
#define FILTx 32
#define KWx   31
#define KTOT  (ENCx + FILTx)     // 544 = 512 mem-k + 31 conv-k + 1 pad
#define KPAD  576                // padded k pitch for g_Bw2
#define BK    32
#define NCH   (KTOT / BK)        // 17
#define BM    64
#define NTILES (Tt / BM)         // 32

// ---------------- scratch ----------------
__device__ float g_pqe[Bx * Ux];
__device__ float g_biasc[Ux];                       // conv_b @ Wle
__device__ float g_pqp[4 * Bx * Ux];                // split-K pq partials
__device__ __align__(128) __nv_bfloat16 g_Bw2[Ux * KPAD];  // K-major: [u][k]
__device__ float g_pA[Bx * NTILES * ENCx];
__device__ float g_pB[Bx * NTILES * ENCx];
__device__ float g_pS[Bx * NTILES];
__device__ float g_pSt[Bx * NTILES];

// ---------------- smem layout (bytes) ----------------
#define BST_STRIDE (256 * 80)            // [n=256][80B row] bf16 per stage
#define BST_OFF 0                        // 2 stages = 40960
#define ABUF_STRIDE (64 * 80)            // [m=64][80B row] bf16 per buffer
#define ABUF_OFF (BST_OFF + 2 * BST_STRIDE)              // 40960
#define PQ_OFF  (ABUF_OFF + 2 * ABUF_STRIDE)             // 51200
#define VA_OFF  (PQ_OFF + 1024)
#define S_OFF   (VA_OFF + 1024)                          // 64 floats
#define ST_OFF  (S_OFF + 256)
#define SE_OFF  (ST_OFF + 256)                           // 95 floats (pad 128)
#define ER_OFF  (SE_OFF + 512)                           // [4][64] floats
#define SM_TOTAL (ER_OFF + 1024)                         // ~54KB -> 2 CTAs/SM

// ---------------- PTX helpers ----------------
#define LDSM_X4(R, addr) \
    asm volatile("ldmatrix.sync.aligned.m8n8.x4.shared.b16 {%0,%1,%2,%3}, [%4];" \
        : "=r"((R)[0]), "=r"((R)[1]), "=r"((R)[2]), "=r"((R)[3]) : "r"(addr))

#define MMA16816(C, A, b0, b1) \
    asm volatile("mma.sync.aligned.m16n8k16.row.col.f32.bf16.bf16.f32 " \
        "{%0,%1,%2,%3},{%4,%5,%6,%7},{%8,%9},{%0,%1,%2,%3};" \
        : "+f"((C)[0]), "+f"((C)[1]), "+f"((C)[2]), "+f"((C)[3]) \
        : "r"((A)[0]), "r"((A)[1]), "r"((A)[2]), "r"((A)[3]), "r"(b0), "r"(b1))

#define CP16(dst, src) \
    asm volatile("cp.async.cg.shared.global [%0], [%1], 16;" :: "r"(dst), "l"(src))
#define CP_COMMIT() asm volatile("cp.async.commit_group;" ::: "memory")
#define CP_WAIT0()  asm volatile("cp.async.wait_group 0;" ::: "memory")

static __device__ __forceinline__ uint32_t smem_u32(const void* p) {
    return (uint32_t)__cvta_generic_to_shared(p);
}
static __device__ __forceinline__ float tanh_fast(float x) {
    float y; asm("tanh.approx.f32 %0, %1;" : "=f"(y) : "f"(x)); return y;
}
static __device__ __forceinline__ uint32_t packbf(float x, float y) {
    __nv_bfloat162 h = __float22bfloat162_rn(make_float2(x, y));
    return *(uint32_t*)&h;
}

// ---------------- setup1: wfold(K-major) + Wle/G/biasc + pq split-K partials ----------------
__global__ __launch_bounds__(256)
void k_setup1(const float* __restrict__ Wm, const float* __restrict__ Wl,
              const float* __restrict__ We, const float* __restrict__ query,
              const float* __restrict__ Wq, const float* __restrict__ conv_w,
              const float* __restrict__ conv_b) {
    __shared__ float sh[8192];
    const int bid = blockIdx.x, tid = threadIdx.x;

    if (bid < 64) {
        const int r0 = bid * 8;          // k rows [r0, r0+8)
        float* w_sm = sh;
        #pragma unroll
        for (int r = 0; r < 8; ++r) w_sm[r * 256 + tid] = Wm[(size_t)(r0 + r) * Ux + tid];
        __syncthreads();
        float acc[8];
        #pragma unroll
        for (int r = 0; r < 8; ++r) acc[r] = 0.f;
        #pragma unroll 1
        for (int v0 = 0; v0 < Ux; v0 += 16) {
            float we[16];
            #pragma unroll
            for (int j = 0; j < 16; ++j) we[j] = We[(size_t)(v0 + j) * Ux + tid];
            #pragma unroll
            for (int j = 0; j < 16; ++j)
                #pragma unroll
                for (int r = 0; r < 8; ++r)
                    acc[r] = fmaf(w_sm[r * 256 + v0 + j], we[j], acc[r]);
        }
        // write K-major: g_Bw2[u=tid][r0..r0+7] as one 16B store
        __nv_bfloat16 pk[8];
        #pragma unroll
        for (int r = 0; r < 8; ++r) pk[r] = __float2bfloat16(acc[r]);
        *(uint4*)&g_Bw2[(size_t)tid * KPAD + r0] = *(uint4*)pk;
    } else if (bid == 64) {
        float* wl_sm = sh;               // [32][256]
        for (int i = tid; i < FILTx * Ux; i += 256) wl_sm[i] = Wl[i];
        __syncthreads();
        float acc[32];
        #pragma unroll
        for (int f = 0; f < 32; ++f) acc[f] = 0.f;
        #pragma unroll 1
        for (int v0 = 0; v0 < Ux; v0 += 8) {
            float we[8];
            #pragma unroll
            for (int j = 0; j < 8; ++j) we[j] = We[(size_t)(v0 + j) * Ux + tid];
            #pragma unroll
            for (int j = 0; j < 8; ++j)
                #pragma unroll
                for (int f = 0; f < 32; ++f)
                    acc[f] = fmaf(wl_sm[f * 256 + v0 + j], we[j], acc[f]);
        }
        __syncthreads();
        #pragma unroll
        for (int f = 0; f < 32; ++f) wl_sm[f * 256 + tid] = acc[f];   // now Wle
        __syncthreads();
        // conv chunk: k = 512..543 (31 G rows + 1 zero pad)
        __nv_bfloat16 pk[32];
        #pragma unroll 1
        for (int k = 0; k < KWx; ++k) {
            float g = 0.f;
            #pragma unroll
            for (int f = 0; f < 32; ++f) g = fmaf(conv_w[f * KWx + k], wl_sm[f * 256 + tid], g);
            pk[k] = __float2bfloat16(g);
        }
        pk[31] = __float2bfloat16(0.f);
        #pragma unroll
        for (int j = 0; j < 4; ++j)
            *(uint4*)&g_Bw2[(size_t)tid * KPAD + ENCx + j * 8] = ((uint4*)pk)[j];
        float bc = 0.f;
        #pragma unroll
        for (int f = 0; f < 32; ++f) bc = fmaf(conv_b[f], wl_sm[f * 256 + tid], bc);
        g_biasc[tid] = bc;
    } else {
        const int i = bid - 65;
        const int b0 = (i >> 2) * 4;
        const int h0 = (i & 3) * 256;
        float* q_sm = sh;                // [4][256]
        #pragma unroll
        for (int j = 0; j < 4; ++j) {
            int idx = j * 256 + tid;
            int bb = idx >> 8, h = idx & 255;
            q_sm[idx] = query[((size_t)(b0 + bb) * 2 + 1) * HIDx + h0 + h];
        }
        __syncthreads();
        float a[4];
        #pragma unroll
        for (int j = 0; j < 4; ++j) a[j] = 0.f;
        #pragma unroll 1
        for (int v0 = 0; v0 < 256; v0 += 16) {
            float wq[16];
            #pragma unroll
            for (int j = 0; j < 16; ++j) wq[j] = Wq[(size_t)(h0 + v0 + j) * Ux + tid];
            #pragma unroll
            for (int j = 0; j < 16; ++j)
                #pragma unroll
                for (int bb = 0; bb < 4; ++bb)
                    a[bb] = fmaf(q_sm[bb * 256 + v0 + j], wq[j], a[bb]);
        }
        #pragma unroll
        for (int bb = 0; bb < 4; ++bb)
            g_pqp[((size_t)(i & 3) * Bx + b0 + bb) * Ux + tid] = a[bb];
    }
}

// ---------------- setup2: combine pq partials, @We, + be ----------------
__global__ __launch_bounds__(256)
void k_setup2(const float* __restrict__ bq, const float* __restrict__ bl,
              const float* __restrict__ bm, const float* __restrict__ We,
              const float* __restrict__ be) {
    __shared__ float t_sm[4][256];
    const int b0 = blockIdx.x * 4, tid = threadIdx.x;
    float base = bq[tid] + bl[tid] + bm[tid];
    #pragma unroll
    for (int bb = 0; bb < 4; ++bb) {
        float t = base;
        #pragma unroll
        for (int s = 0; s < 4; ++s) t += g_pqp[((size_t)s * Bx + b0 + bb) * Ux + tid];
        t_sm[bb][tid] = t;
    }
    __syncthreads();
    float c[4];
    #pragma unroll
    for (int bb = 0; bb < 4; ++bb) c[bb] = be[tid];
    #pragma unroll 1
    for (int v0 = 0; v0 < Ux; v0 += 16) {
        float we[16];
        #pragma unroll
        for (int j = 0; j < 16; ++j) we[j] = We[(size_t)(v0 + j) * Ux + tid];
        #pragma unroll
        for (int j = 0; j < 16; ++j)
            #pragma unroll
            for (int bb = 0; bb < 4; ++bb)
                c[bb] = fmaf(t_sm[bb][v0 + j], we[j], c[bb]);
    }
    #pragma unroll
    for (int bb = 0; bb < 4; ++bb) g_pqe[(size_t)(b0 + bb) * Ux + tid] = c[bb];
}

// ---------------- main: BM=64, 2 CTAs/SM, all non-trans ldmatrix ----------------
// Block = (b, 64-row t-tile), 512 threads, 16 warps (4m x 4n), warp = 16m x 64n.
__global__ __launch_bounds__(512, 2)
void k_main(const float* __restrict__ memory, const float* __restrict__ state,
            const float* __restrict__ v_a) {
    extern __shared__ char smem[];
    const int b    = blockIdx.x >> 5;
    const int tile = blockIdx.x & 31;
    const int t0   = tile * BM;
    const int tid  = threadIdx.x;
    const int lane = tid & 31;
    const int warp = tid >> 5;
    const int wm   = warp >> 2;                 // 0..3 (16 rows each)
    const int wn   = warp & 3;                  // 0..3 (64 cols each)

    float* pq_sm = (float*)(smem + PQ_OFF);
    float* va_sm = (float*)(smem + VA_OFF);
    float* s_sm  = (float*)(smem + S_OFF);
    float* st_sm = (float*)(smem + ST_OFF);
    float* se    = (float*)(smem + SE_OFF);
    float* e_red = (float*)(smem + ER_OFF);     // [4][64]

    if (tid < Ux) {
        pq_sm[tid] = g_pqe[b * Ux + tid] + g_biasc[tid];
        va_sm[tid] = v_a[tid];
    }
    if (tid < BM) st_sm[tid] = state[b * Tt + t0 + tid];
    if (tid < BM + 31) {
        int t = t0 + tid - 15;
        se[tid] = (t >= 0 && t < Tt) ? state[b * Tt + t] : 0.f;
    }

    const float* memb = memory + ((size_t)(b * Tt + t0)) * ENCx;
    const char*  bwp  = (const char*)g_Bw2;
    const uint32_t smb = smem_u32(smem);

    // B copy: chunk c -> stage (16KB data over 256 rows x 64B; 2 CP16/thread)
    auto copyB = [&](int c, int stage) {
        #pragma unroll
        for (int j = 0; j < 2; ++j) {
            int u = j * 512 + tid;               // 1024 16B units (256 rows x 4)
            int row = u >> 2, c16 = u & 3;
            uint32_t dst = smb + BST_OFF + stage * BST_STRIDE + row * 80 + c16 * 16;
            const char* src = bwp + (size_t)row * (KPAD * 2) + c * 64 + c16 * 16;
            CP16(dst, src);
        }
    };

    __syncthreads();                             // se/st/pq visible

    copyB(0, 0); CP_COMMIT();

    // A prefetch: 1 float4 per thread covers the 64x32 chunk
    const int arow = tid >> 3, ac4 = tid & 7;
    float4 aReg = *(const float4*)&memb[(size_t)arow * ENCx + ac4 * 4];

    float acc[8][4];
    #pragma unroll
    for (int i = 0; i < 8; ++i) { acc[i][0]=0.f; acc[i][1]=0.f; acc[i][2]=0.f; acc[i][3]=0.f; }

    // per-warp ldmatrix lane offsets (A and B, both non-trans)
    const uint32_t a_off = (uint32_t)((lane & 15)) * 80 + ((lane >> 4) << 4);
    const uint32_t b_off = (uint32_t)((lane & 7) + ((lane >> 4) << 3)) * 80
                         + (((lane >> 3) & 1) << 4);

    #pragma unroll 1
    for (int c = 0; c < NCH; ++c) {
        const int stage = c & 1;
        const int abuf  = c & 1;
        char* Ab = smem + ABUF_OFF + abuf * ABUF_STRIDE;

        // 1. store A chunk c (bf16) into Ab
        if (c < 16) {
            uint2 pk;
            pk.x = packbf(aReg.x, aReg.y);
            pk.y = packbf(aReg.z, aReg.w);
            *(uint2*)(Ab + arow * 80 + ac4 * 8) = pk;
        } else {
            float v[4];
            #pragma unroll
            for (int e = 0; e < 4; ++e) {
                int k = ac4 * 4 + e;
                v[e] = (k < KWx) ? se[arow + k] : 0.f;
            }
            uint2 pk;
            pk.x = packbf(v[0], v[1]);
            pk.y = packbf(v[2], v[3]);
            *(uint2*)(Ab + arow * 80 + ac4 * 8) = pk;
        }

        // 2. wait B chunk c, single barrier per chunk
        CP_WAIT0();
        __syncthreads();

        // 3. prefetch A chunk c+1; issue B copy c+1 (stage safe: readers passed the sync)
        if (c + 1 < 16)
            aReg = *(const float4*)&memb[(size_t)arow * ENCx + (c + 1) * 32 + ac4 * 4];
        if (c + 1 < NCH) copyB(c + 1, (c + 1) & 1);
        CP_COMMIT();

        // 4. compute chunk c
        const uint32_t abase = smb + ABUF_OFF + abuf * ABUF_STRIDE;
        const uint32_t bst   = smb + BST_OFF + stage * BST_STRIDE;

        #pragma unroll
        for (int ks = 0; ks < 2; ++ks) {
            uint32_t a0[4];
            LDSM_X4(a0, abase + (uint32_t)(wm * 16) * 80 + ks * 32 + a_off);
            #pragma unroll
            for (int p = 0; p < 4; ++p) {
                uint32_t bf[4];
                uint32_t baddr = bst + (uint32_t)(wn * 64 + p * 16) * 80 + ks * 32 + b_off;
                LDSM_X4(bf, baddr);
                MMA16816(acc[2 * p],     a0, bf[0], bf[1]);
                MMA16816(acc[2 * p + 1], a0, bf[2], bf[3]);
            }
        }
    }

    // ---- epilogue: tanh (MUFU), v_a dot, per-row energy reduce ----
    {
        float e0 = 0.f, e1 = 0.f;
        #pragma unroll
        for (int nt = 0; nt < 8; ++nt) {
            const float* cc = acc[nt];
            int u0 = wn * 64 + nt * 8 + (lane & 3) * 2;
            e0 = fmaf(va_sm[u0],     tanh_fast(cc[0] + pq_sm[u0]),     e0);
            e0 = fmaf(va_sm[u0 + 1], tanh_fast(cc[1] + pq_sm[u0 + 1]), e0);
            e1 = fmaf(va_sm[u0],     tanh_fast(cc[2] + pq_sm[u0]),     e1);
            e1 = fmaf(va_sm[u0 + 1], tanh_fast(cc[3] + pq_sm[u0 + 1]), e1);
        }
        e0 += __shfl_xor_sync(0xffffffffu, e0, 1);
        e0 += __shfl_xor_sync(0xffffffffu, e0, 2);
        e1 += __shfl_xor_sync(0xffffffffu, e1, 1);
        e1 += __shfl_xor_sync(0xffffffffu, e1, 2);
        if ((lane & 3) == 0) {
            int row = wm * 16 + (lane >> 2);
            e_red[wn * 64 + row]     = e0;
            e_red[wn * 64 + row + 8] = e1;
        }
    }
    __syncthreads();
    if (tid < BM) {
        float E = e_red[tid] + e_red[64 + tid] + e_red[128 + tid] + e_red[192 + tid];
        s_sm[tid] = 1.f / (1.f + __expf(-E));
    }
    __syncthreads();

    if (tid < 32) {
        float S  = s_sm[tid]  + s_sm[tid + 32];
        float St = st_sm[tid] + st_sm[tid + 32];
        #pragma unroll
        for (int off = 16; off > 0; off >>= 1) {
            S  += __shfl_xor_sync(0xffffffffu, S, off);
            St += __shfl_xor_sync(0xffffffffu, St, off);
        }
        if (tid == 0) {
            g_pS[b * NTILES + tile]  = S;
            g_pSt[b * NTILES + tile] = St;
        }
    }

    // ---- weighted memory column sums: 1 column per thread ----
    float aA0 = 0.f, aB0 = 0.f, aA1 = 0.f, aB1 = 0.f;
    const float* p = memb + tid;
    #pragma unroll 8
    for (int m = 0; m < BM; m += 2) {
        float v0 = p[(size_t)m * ENCx];
        float v1 = p[(size_t)(m + 1) * ENCx];
        aA0 = fmaf(st_sm[m],     v0, aA0);
        aB0 = fmaf(s_sm[m],      v0, aB0);
        aA1 = fmaf(st_sm[m + 1], v1, aA1);
        aB1 = fmaf(s_sm[m + 1],  v1, aB1);
    }
    size_t base = (size_t)(b * NTILES + tile) * ENCx;
    g_pA[base + tid] = aA0 + aA1;
    g_pB[base + tid] = aB0 + aB1;
}

// ---------------- finalize: 1024 threads, e-split GEMM ----------------
__global__ __launch_bounds__(1024)
void k_final(const float* __restrict__ Wm, const float* __restrict__ bm,
             float* __restrict__ out) {
    __shared__ float M[ENCx];
    __shared__ float sS[2];
    __shared__ float part[3][Ux];
    const int b = blockIdx.x, tid = threadIdx.x;   // 1024 threads
    const int q = tid >> 8, u = tid & 255;

    if (tid < 32) {
        float S  = g_pS[b * NTILES + tid];
        float St = g_pSt[b * NTILES + tid];
        #pragma unroll
        for (int off = 16; off > 0; off >>= 1) {
            S  += __shfl_xor_sync(0xffffffffu, S, off);
            St += __shfl_xor_sync(0xffffffffu, St, off);
        }
        if (tid == 0) { sS[0] = S; sS[1] = St; }
    }

    float a = 0.f, bb = 0.f;
    if (tid < ENCx) {
        #pragma unroll
        for (int t = 0; t < NTILES; ++t) {
            a  += g_pA[(size_t)(b * NTILES + t) * ENCx + tid];
            bb += g_pB[(size_t)(b * NTILES + t) * ENCx + tid];
        }
    }
    __syncthreads();
    if (tid < ENCx) M[tid] = a + bb * (1.f / sS[0]);
    __syncthreads();

    // GEMM quarter: e in [q*128, q*128+128)
    float acc = 0.f;
    #pragma unroll 1
    for (int e0 = q * 128; e0 < q * 128 + 128; e0 += 8) {
        float wv[8];
        #pragma unroll
        for (int j = 0; j < 8; ++j) wv[j] = Wm[(size_t)(e0 + j) * Ux + u];
        #pragma unroll
        for (int j = 0; j < 8; ++j) acc = fmaf(M[e0 + j], wv[j], acc);
    }
    if (q > 0) part[q - 1][u] = acc;
    __syncthreads();
    if (q == 0) {
        float cumsum = sS[1] + 1.f;
        out[b * Ux + u] = fmaf(cumsum, bm[u],
                               acc + part[0][u] + part[1][u] + part[2][u]);
    }
}

// ---------------- launch ----------------
extern "C" void kernel_launch(void* const* d_in, const int* in_sizes, int n_in,
                              void* d_out, int out_size) {
    const float* query  = (const float*)d_in[0];
    const float* state  = (const float*)d_in[1];
    const float* memory = (const float*)d_in[2];
    const float* Wq     = (const float*)d_in[3];
    const float* bq     = (const float*)d_in[4];
    const float* Wm     = (const float*)d_in[5];
    const float* bm     = (const float*)d_in[6];
    const float* Wl     = (const float*)d_in[7];
    const float* bl     = (const float*)d_in[8];
    const float* conv_w = (const float*)d_in[9];
    const float* conv_b = (const float*)d_in[10];
    const float* We     = (const float*)d_in[11];
    const float* be     = (const float*)d_in[12];
    const float* v_a    = (const float*)d_in[13];
    float* out = (float*)d_out;

    cudaFuncSetAttribute(k_main, cudaFuncAttributeMaxDynamicSharedMemorySize, SM_TOTAL);

    k_setup1<<<129, 256>>>(Wm, Wl, We, query, Wq, conv_w, conv_b);
    k_setup2<<<16, 256>>>(bq, bl, bm, We, be);
    k_main<<<Bx * NTILES, 512, SM_TOTAL>>>(memory, state, v_a);
    k_final<<<Bx, 1024>>>(Wm, bm, out);
}

// round 16
// speedup vs baseline: 1.0055x; 1.0055x over previous
#include <cuda_runtime.h>
#include <cuda_bf16.h>
#include <math.h>
#include <stdint.h>

// Problem constants
#define Bx    64
#define Tt    2048
#define HIDx  1024
#define ENCx  512
#define Ux    256
#define FILTx 32
#define KWx   31
#define KTOT  (ENCx + FILTx)     // 544 = 512 mem-k + 31 conv-k + 1 pad
#define BK    32
#define NCH   (KTOT / BK)        // 17
#define BM    64
#define NTILES (Tt / BM)         // 32

// ---------------- scratch ----------------
__device__ float g_pqe[Bx * Ux];
__device__ float g_biasc[Ux];                       // conv_b @ Wle
__device__ float g_pqp[4 * Bx * Ux];                // split-K pq partials
__device__ __align__(128) __nv_bfloat16 g_Bw[KTOT * Ux];   // [Wm@We(512); G(31); 0]
__device__ float g_pA[Bx * NTILES * ENCx];
__device__ float g_pB[Bx * NTILES * ENCx];
__device__ float g_pS[Bx * NTILES];
__device__ float g_pSt[Bx * NTILES];
__device__ float g_mA[Bx * ENCx];                   // merged partials
__device__ float g_mB[Bx * ENCx];

// ---------------- smem layout (bytes) ----------------
#define BST_STRIDE (32 * 264 * 2)        // [32][264] bf16 per stage (528B rows)
#define BST_OFF 0                        // 2 stages = 33792
#define ABUF_STRIDE (64 * 40 * 2)        // [64][40] bf16 per buffer (80B rows)
#define ABUF_OFF (BST_OFF + 2 * BST_STRIDE)              // 33792
#define PQ_OFF  (ABUF_OFF + 2 * ABUF_STRIDE)             // 44032
#define VA_OFF  (PQ_OFF + 1024)
#define S_OFF   (VA_OFF + 1024)                          // 64 floats
#define ST_OFF  (S_OFF + 256)
#define SE_OFF  (ST_OFF + 256)                           // 95 floats (pad 128)
#define ER_OFF  (SE_OFF + 512)                           // [4][64] floats
#define SM_TOTAL (ER_OFF + 1024)                         // ~47KB -> 2 CTAs/SM

// ---------------- PTX helpers ----------------
#define LDSM_X4(R, addr) \
    asm volatile("ldmatrix.sync.aligned.m8n8.x4.shared.b16 {%0,%1,%2,%3}, [%4];" \
        : "=r"((R)[0]), "=r"((R)[1]), "=r"((R)[2]), "=r"((R)[3]) : "r"(addr))

#define LDSM_X4T(R, addr) \
    asm volatile("ldmatrix.sync.aligned.m8n8.x4.trans.shared.b16 {%0,%1,%2,%3}, [%4];" \
        : "=r"((R)[0]), "=r"((R)[1]), "=r"((R)[2]), "=r"((R)[3]) : "r"(addr))

#define MMA16816(C, A, b0, b1) \
    asm volatile("mma.sync.aligned.m16n8k16.row.col.f32.bf16.bf16.f32 " \
        "{%0,%1,%2,%3},{%4,%5,%6,%7},{%8,%9},{%0,%1,%2,%3};" \
        : "+f"((C)[0]), "+f"((C)[1]), "+f"((C)[2]), "+f"((C)[3]) \
        : "r"((A)[0]), "r"((A)[1]), "r"((A)[2]), "r"((A)[3]), "r"(b0), "r"(b1))

#define CP16(dst, src) \
    asm volatile("cp.async.cg.shared.global [%0], [%1], 16;" :: "r"(dst), "l"(src))
#define CP_COMMIT() asm volatile("cp.async.commit_group;" ::: "memory")
#define CP_WAIT0()  asm volatile("cp.async.wait_group 0;" ::: "memory")

static __device__ __forceinline__ uint32_t smem_u32(const void* p) {
    return (uint32_t)__cvta_generic_to_shared(p);
}
static __device__ __forceinline__ float tanh_fast(float x) {
    float y; asm("tanh.approx.f32 %0, %1;" : "=f"(y) : "f"(x)); return y;
}
static __device__ __forceinline__ uint32_t packbf(float x, float y) {
    __nv_bfloat162 h = __float22bfloat162_rn(make_float2(x, y));
    return *(uint32_t*)&h;
}

// ---------------- setup1: wfold + Wle/G/biasc + pq split-K partials ----------------
__global__ __launch_bounds__(256)
void k_setup1(const float* __restrict__ Wm, const float* __restrict__ Wl,
              const float* __restrict__ We, const float* __restrict__ query,
              const float* __restrict__ Wq, const float* __restrict__ conv_w,
              const float* __restrict__ conv_b) {
    __shared__ float sh[8192];
    const int bid = blockIdx.x, tid = threadIdx.x;

    if (bid < 64) {
        const int r0 = bid * 8;
        float* w_sm = sh;
        #pragma unroll
        for (int r = 0; r < 8; ++r) w_sm[r * 256 + tid] = Wm[(size_t)(r0 + r) * Ux + tid];
        __syncthreads();
        float acc[8];
        #pragma unroll
        for (int r = 0; r < 8; ++r) acc[r] = 0.f;
        #pragma unroll 1
        for (int v0 = 0; v0 < Ux; v0 += 16) {
            float we[16];
            #pragma unroll
            for (int j = 0; j < 16; ++j) we[j] = We[(size_t)(v0 + j) * Ux + tid];
            #pragma unroll
            for (int j = 0; j < 16; ++j)
                #pragma unroll
                for (int r = 0; r < 8; ++r)
                    acc[r] = fmaf(w_sm[r * 256 + v0 + j], we[j], acc[r]);
        }
        #pragma unroll
        for (int r = 0; r < 8; ++r)
            g_Bw[(size_t)(r0 + r) * Ux + tid] = __float2bfloat16(acc[r]);
    } else if (bid == 64) {
        float* wl_sm = sh;               // [32][256]
        for (int i = tid; i < FILTx * Ux; i += 256) wl_sm[i] = Wl[i];
        __syncthreads();
        float acc[32];
        #pragma unroll
        for (int f = 0; f < 32; ++f) acc[f] = 0.f;
        #pragma unroll 1
        for (int v0 = 0; v0 < Ux; v0 += 8) {
            float we[8];
            #pragma unroll
            for (int j = 0; j < 8; ++j) we[j] = We[(size_t)(v0 + j) * Ux + tid];
            #pragma unroll
            for (int j = 0; j < 8; ++j)
                #pragma unroll
                for (int f = 0; f < 32; ++f)
                    acc[f] = fmaf(wl_sm[f * 256 + v0 + j], we[j], acc[f]);
        }
        __syncthreads();
        #pragma unroll
        for (int f = 0; f < 32; ++f) wl_sm[f * 256 + tid] = acc[f];   // now Wle
        __syncthreads();
        #pragma unroll 1
        for (int k = 0; k < KWx; ++k) {
            float g = 0.f;
            #pragma unroll
            for (int f = 0; f < 32; ++f) g = fmaf(conv_w[f * KWx + k], wl_sm[f * 256 + tid], g);
            g_Bw[(size_t)(ENCx + k) * Ux + tid] = __float2bfloat16(g);
        }
        g_Bw[(size_t)(KTOT - 1) * Ux + tid] = __float2bfloat16(0.f);  // pad row
        float bc = 0.f;
        #pragma unroll
        for (int f = 0; f < 32; ++f) bc = fmaf(conv_b[f], wl_sm[f * 256 + tid], bc);
        g_biasc[tid] = bc;
    } else {
        const int i = bid - 65;
        const int b0 = (i >> 2) * 4;
        const int h0 = (i & 3) * 256;
        float* q_sm = sh;                // [4][256]
        #pragma unroll
        for (int j = 0; j < 4; ++j) {
            int idx = j * 256 + tid;
            int bb = idx >> 8, h = idx & 255;
            q_sm[idx] = query[((size_t)(b0 + bb) * 2 + 1) * HIDx + h0 + h];
        }
        __syncthreads();
        float a[4];
        #pragma unroll
        for (int j = 0; j < 4; ++j) a[j] = 0.f;
        #pragma unroll 1
        for (int v0 = 0; v0 < 256; v0 += 16) {
            float wq[16];
            #pragma unroll
            for (int j = 0; j < 16; ++j) wq[j] = Wq[(size_t)(h0 + v0 + j) * Ux + tid];
            #pragma unroll
            for (int j = 0; j < 16; ++j)
                #pragma unroll
                for (int bb = 0; bb < 4; ++bb)
                    a[bb] = fmaf(q_sm[bb * 256 + v0 + j], wq[j], a[bb]);
        }
        #pragma unroll
        for (int bb = 0; bb < 4; ++bb)
            g_pqp[((size_t)(i & 3) * Bx + b0 + bb) * Ux + tid] = a[bb];
    }
}

// ---------------- setup2: combine pq partials, @We, + be ----------------
__global__ __launch_bounds__(256)
void k_setup2(const float* __restrict__ bq, const float* __restrict__ bl,
              const float* __restrict__ bm, const float* __restrict__ We,
              const float* __restrict__ be) {
    __shared__ float t_sm[4][256];
    const int b0 = blockIdx.x * 4, tid = threadIdx.x;
    float base = bq[tid] + bl[tid] + bm[tid];
    #pragma unroll
    for (int bb = 0; bb < 4; ++bb) {
        float t = base;
        #pragma unroll
        for (int s = 0; s < 4; ++s) t += g_pqp[((size_t)s * Bx + b0 + bb) * Ux + tid];
        t_sm[bb][tid] = t;
    }
    __syncthreads();
    float c[4];
    #pragma unroll
    for (int bb = 0; bb < 4; ++bb) c[bb] = be[tid];
    #pragma unroll 1
    for (int v0 = 0; v0 < Ux; v0 += 16) {
        float we[16];
        #pragma unroll
        for (int j = 0; j < 16; ++j) we[j] = We[(size_t)(v0 + j) * Ux + tid];
        #pragma unroll
        for (int j = 0; j < 16; ++j)
            #pragma unroll
            for (int bb = 0; bb < 4; ++bb)
                c[bb] = fmaf(t_sm[bb][v0 + j], we[j], c[bb]);
    }
    #pragma unroll
    for (int bb = 0; bb < 4; ++bb) g_pqe[(size_t)(b0 + bb) * Ux + tid] = c[bb];
}

// ---------------- alignment no-op (makes k_main launch #4 for ncu capture) ----------------
__global__ void k_noop() {}

// ---------------- main: BM=64, 2 CTAs/SM, bf16 mma.sync (round-14 best) ----------------
// Block = (b, 64-row t-tile), 512 threads, 16 warps (4m x 4n), warp = 16m x 64n.
__global__ __launch_bounds__(512, 2)
void k_main(const float* __restrict__ memory, const float* __restrict__ state,
            const float* __restrict__ v_a) {
    extern __shared__ char smem[];
    const int b    = blockIdx.x >> 5;
    const int tile = blockIdx.x & 31;
    const int t0   = tile * BM;
    const int tid  = threadIdx.x;
    const int lane = tid & 31;
    const int warp = tid >> 5;
    const int wm   = warp >> 2;                 // 0..3 (16 rows each)
    const int wn   = warp & 3;                  // 0..3 (64 cols each)

    float* pq_sm = (float*)(smem + PQ_OFF);
    float* va_sm = (float*)(smem + VA_OFF);
    float* s_sm  = (float*)(smem + S_OFF);
    float* st_sm = (float*)(smem + ST_OFF);
    float* se    = (float*)(smem + SE_OFF);
    float* e_red = (float*)(smem + ER_OFF);     // [4][64]

    if (tid < Ux) {
        pq_sm[tid] = g_pqe[b * Ux + tid] + g_biasc[tid];
        va_sm[tid] = v_a[tid];
    }
    if (tid < BM) st_sm[tid] = state[b * Tt + t0 + tid];
    if (tid < BM + 31) {
        int t = t0 + tid - 15;
        se[tid] = (t >= 0 && t < Tt) ? state[b * Tt + t] : 0.f;
    }

    const float* memb = memory + ((size_t)(b * Tt + t0)) * ENCx;
    const char*  bwp  = (const char*)g_Bw;
    const uint32_t smb = smem_u32(smem);

    // B copy: chunk c -> stage (16KB, 2 CP16/thread)
    auto copyB = [&](int c, int stage) {
        #pragma unroll
        for (int j = 0; j < 2; ++j) {
            int u = j * 512 + tid;               // 1024 16B units (32 rows x 32)
            int row = u >> 5, c16 = u & 31;
            uint32_t dst = smb + BST_OFF + stage * BST_STRIDE + row * 528 + c16 * 16;
            const char* src = bwp + (size_t)(c * 32 + row) * 512 + c16 * 16;
            CP16(dst, src);
        }
    };

    __syncthreads();                             // se/st/pq visible

    copyB(0, 0); CP_COMMIT();

    // A prefetch: 1 float4 per thread covers the 64x32 chunk
    const int arow = tid >> 3, ac4 = tid & 7;
    float4 aReg = *(const float4*)&memb[(size_t)arow * ENCx + ac4 * 4];

    float acc[8][4];
    #pragma unroll
    for (int i = 0; i < 8; ++i) { acc[i][0]=0.f; acc[i][1]=0.f; acc[i][2]=0.f; acc[i][3]=0.f; }

    #pragma unroll 1
    for (int c = 0; c < NCH; ++c) {
        const int stage = c & 1;
        const int abuf  = c & 1;
        char* Ab = smem + ABUF_OFF + abuf * ABUF_STRIDE;

        // 1. store A chunk c (bf16) into Ab
        if (c < 16) {
            uint2 pk;
            pk.x = packbf(aReg.x, aReg.y);
            pk.y = packbf(aReg.z, aReg.w);
            *(uint2*)(Ab + arow * 80 + ac4 * 8) = pk;
        } else {
            float v[4];
            #pragma unroll
            for (int e = 0; e < 4; ++e) {
                int k = ac4 * 4 + e;
                v[e] = (k < KWx) ? se[arow + k] : 0.f;
            }
            uint2 pk;
            pk.x = packbf(v[0], v[1]);
            pk.y = packbf(v[2], v[3]);
            *(uint2*)(Ab + arow * 80 + ac4 * 8) = pk;
        }

        // 2. wait B chunk c, make everything visible
        CP_WAIT0();
        __syncthreads();

        // 3. prefetch A chunk c+1; issue B copy c+1 (stage now safe to overwrite)
        if (c + 1 < 16)
            aReg = *(const float4*)&memb[(size_t)arow * ENCx + (c + 1) * 32 + ac4 * 4];
        if (c + 1 < NCH) copyB(c + 1, (c + 1) & 1);
        CP_COMMIT();

        // 4. compute chunk c
        const uint32_t abase = smb + ABUF_OFF + abuf * ABUF_STRIDE;
        const uint32_t bst   = smb + BST_OFF + stage * BST_STRIDE;

        #pragma unroll
        for (int ks = 0; ks < 2; ++ks) {
            uint32_t a0[4];
            LDSM_X4(a0, abase + (uint32_t)(wm * 16 + (lane & 15)) * 80
                        + ks * 32 + ((lane >> 4) << 4));
            #pragma unroll
            for (int p = 0; p < 4; ++p) {
                uint32_t bf[4];
                uint32_t baddr = bst + (uint32_t)(ks * 16 + (lane & 15)) * 528
                               + (uint32_t)(wn * 64 + p * 16 + ((lane >> 4) << 3)) * 2;
                LDSM_X4T(bf, baddr);
                MMA16816(acc[2 * p],     a0, bf[0], bf[1]);
                MMA16816(acc[2 * p + 1], a0, bf[2], bf[3]);
            }
        }
        // barrier at next iter's step 2 gates stage/Ab reuse
        __syncthreads();
    }

    // ---- epilogue: tanh (MUFU), v_a dot, per-row energy reduce ----
    {
        float e0 = 0.f, e1 = 0.f;
        #pragma unroll
        for (int nt = 0; nt < 8; ++nt) {
            const float* cc = acc[nt];
            int u0 = wn * 64 + nt * 8 + (lane & 3) * 2;
            e0 = fmaf(va_sm[u0],     tanh_fast(cc[0] + pq_sm[u0]),     e0);
            e0 = fmaf(va_sm[u0 + 1], tanh_fast(cc[1] + pq_sm[u0 + 1]), e0);
            e1 = fmaf(va_sm[u0],     tanh_fast(cc[2] + pq_sm[u0]),     e1);
            e1 = fmaf(va_sm[u0 + 1], tanh_fast(cc[3] + pq_sm[u0 + 1]), e1);
        }
        e0 += __shfl_xor_sync(0xffffffffu, e0, 1);
        e0 += __shfl_xor_sync(0xffffffffu, e0, 2);
        e1 += __shfl_xor_sync(0xffffffffu, e1, 1);
        e1 += __shfl_xor_sync(0xffffffffu, e1, 2);
        if ((lane & 3) == 0) {
            int row = wm * 16 + (lane >> 2);
            e_red[wn * 64 + row]     = e0;
            e_red[wn * 64 + row + 8] = e1;
        }
    }
    __syncthreads();
    if (tid < BM) {
        float E = e_red[tid] + e_red[64 + tid] + e_red[128 + tid] + e_red[192 + tid];
        s_sm[tid] = 1.f / (1.f + __expf(-E));
    }
    __syncthreads();

    if (tid < 32) {
        float S  = s_sm[tid]  + s_sm[tid + 32];
        float St = st_sm[tid] + st_sm[tid + 32];
        #pragma unroll
        for (int off = 16; off > 0; off >>= 1) {
            S  += __shfl_xor_sync(0xffffffffu, S, off);
            St += __shfl_xor_sync(0xffffffffu, St, off);
        }
        if (tid == 0) {
            g_pS[b * NTILES + tile]  = S;
            g_pSt[b * NTILES + tile] = St;
        }
    }

    // ---- weighted memory column sums: 1 column per thread, MLP-4 ----
    float aA0 = 0.f, aB0 = 0.f, aA1 = 0.f, aB1 = 0.f;
    const float* p = memb + tid;
    #pragma unroll 8
    for (int m = 0; m < BM; m += 2) {
        float v0 = p[(size_t)m * ENCx];
        float v1 = p[(size_t)(m + 1) * ENCx];
        aA0 = fmaf(st_sm[m],     v0, aA0);
        aB0 = fmaf(s_sm[m],      v0, aB0);
        aA1 = fmaf(st_sm[m + 1], v1, aA1);
        aB1 = fmaf(s_sm[m + 1],  v1, aB1);
    }
    size_t base = (size_t)(b * NTILES + tile) * ENCx;
    g_pA[base + tid] = aA0 + aA1;
    g_pB[base + tid] = aB0 + aB1;
}

// ---------------- k_red: merge tile partials, 4 blocks per batch ----------------
// grid 256: bid>>2 = b, bid&3 = quarter of e-range. 256 threads: 2 per e-column.
__global__ __launch_bounds__(256)
void k_red() {
    __shared__ float shA[128], shB[128];
    const int b = blockIdx.x >> 2, q = blockIdx.x & 3;
    const int tid = threadIdx.x;
    const int e = q * 128 + (tid & 127);        // e column
    const int h = tid >> 7;                     // tile half: 0 -> 0..15, 1 -> 16..31

    float a = 0.f, bb = 0.f;
    const float* pA = g_pA + (size_t)(b * NTILES + h * 16) * ENCx + e;
    const float* pB = g_pB + (size_t)(b * NTILES + h * 16) * ENCx + e;
    #pragma unroll
    for (int t = 0; t < 16; ++t) {
        a  += pA[(size_t)t * ENCx];
        bb += pB[(size_t)t * ENCx];
    }
    if (h == 1) { shA[tid & 127] = a; shB[tid & 127] = bb; }
    __syncthreads();
    if (h == 0) {
        g_mA[b * ENCx + e] = a + shA[tid];
        g_mB[b * ENCx + e] = bb + shB[tid];
    }
}

// ---------------- k_ctx: S/St reduce + M build + 512x256 GEMM ----------------
__global__ __launch_bounds__(512)
void k_ctx(const float* __restrict__ Wm, const float* __restrict__ bm,
           float* __restrict__ out) {
    __shared__ float M[ENCx];
    __shared__ float sS[2];
    __shared__ float part[Ux];
    const int b = blockIdx.x, tid = threadIdx.x;   // 512 threads
    const int half = tid >> 8, u = tid & 255;

    if (tid < 32) {
        float S  = g_pS[b * NTILES + tid];
        float St = g_pSt[b * NTILES + tid];
        #pragma unroll
        for (int off = 16; off > 0; off >>= 1) {
            S  += __shfl_xor_sync(0xffffffffu, S, off);
            St += __shfl_xor_sync(0xffffffffu, St, off);
        }
        if (tid == 0) { sS[0] = S; sS[1] = St; }
    }
    float a  = g_mA[b * ENCx + tid];
    float bb = g_mB[b * ENCx + tid];
    __syncthreads();
    M[tid] = a + bb * (1.f / sS[0]);
    __syncthreads();

    float acc = 0.f;
    #pragma unroll 1
    for (int e0 = half * 256; e0 < half * 256 + 256; e0 += 8) {
        float wv[8];
        #pragma unroll
        for (int j = 0; j < 8; ++j) wv[j] = Wm[(size_t)(e0 + j) * Ux + u];
        #pragma unroll
        for (int j = 0; j < 8; ++j) acc = fmaf(M[e0 + j], wv[j], acc);
    }
    if (half == 1) part[u] = acc;
    __syncthreads();
    if (half == 0) {
        float cumsum = sS[1] + 1.f;
        out[b * Ux + u] = fmaf(cumsum, bm[u], acc + part[u]);
    }
}

// ---------------- launch ----------------
extern "C" void kernel_launch(void* const* d_in, const int* in_sizes, int n_in,
                              void* d_out, int out_size) {
    const float* query  = (const float*)d_in[0];
    const float* state  = (const float*)d_in[1];
    const float* memory = (const float*)d_in[2];
    const float* Wq     = (const float*)d_in[3];
    const float* bq     = (const float*)d_in[4];
    const float* Wm     = (const float*)d_in[5];
    const float* bm     = (const float*)d_in[6];
    const float* Wl     = (const float*)d_in[7];
    const float* bl     = (const float*)d_in[8];
    const float* conv_w = (const float*)d_in[9];
    const float* conv_b = (const float*)d_in[10];
    const float* We     = (const float*)d_in[11];
    const float* be     = (const float*)d_in[12];
    const float* v_a    = (const float*)d_in[13];
    float* out = (float*)d_out;

    cudaFuncSetAttribute(k_main, cudaFuncAttributeMaxDynamicSharedMemorySize, SM_TOTAL);

    k_setup1<<<129, 256>>>(Wm, Wl, We, query, Wq, conv_w, conv_b);
    k_setup2<<<16, 256>>>(bq, bl, bm, We, be);
    k_noop<<<1, 32>>>();                                   // aligns k_main to launch #4 for ncu
    k_main<<<Bx * NTILES, 512, SM_TOTAL>>>(memory, state, v_a);
    k_red<<<4 * Bx, 256>>>();
    k_ctx<<<Bx, 512>>>(Wm, bm, out);
}

// round 17
// speedup vs baseline: 1.1416x; 1.1354x over previous
#include <cuda_runtime.h>
#include <cuda_bf16.h>
#include <math.h>
#include <stdint.h>

// Problem constants
#define Bx    64
#define Tt    2048
#define HIDx  1024
#define ENCx  512
#define Ux    256
#define FILTx 32
#define KWx   31
#define KTOT  (ENCx + FILTx)     // 544 = 512 mem-k + 31 conv-k + 1 pad
#define BK    32
#define NCH   (KTOT / BK)        // 17
#define BM    64
#define NTILES (Tt / BM)         // 32

// ---------------- scratch ----------------
__device__ float g_pqe[Bx * Ux];
__device__ float g_biasc[Ux];                       // conv_b @ Wle
__device__ float g_pqp[4 * Bx * Ux];                // split-K pq partials
__device__ __align__(128) __nv_bfloat16 g_Bw[KTOT * Ux];   // [Wm@We(512); G(31); 0]
__device__ float g_pA[Bx * NTILES * ENCx];
__device__ float g_pB[Bx * NTILES * ENCx];
__device__ float g_pS[Bx * NTILES];
__device__ float g_pSt[Bx * NTILES];

// ---------------- smem layout (bytes) ----------------
#define BST_STRIDE (32 * 264 * 2)        // [32][264] bf16 per stage (528B rows)
#define BST_OFF 0                        // 2 stages = 33792
#define ABUF_STRIDE (64 * 40 * 2)        // [64][40] bf16 per buffer (80B rows)
#define ABUF_OFF (BST_OFF + 2 * BST_STRIDE)              // 33792
#define PQ_OFF  (ABUF_OFF + 2 * ABUF_STRIDE)             // 44032
#define VA_OFF  (PQ_OFF + 1024)
#define S_OFF   (VA_OFF + 1024)                          // 64 floats
#define ST_OFF  (S_OFF + 256)
#define SE_OFF  (ST_OFF + 256)                           // 95 floats (pad 128)
#define ER_OFF  (SE_OFF + 512)                           // [4][64] floats
#define SM_TOTAL (ER_OFF + 1024)                         // ~47KB -> 2 CTAs/SM

// ---------------- PTX helpers ----------------
#define LDSM_X4(R, addr) \
    asm volatile("ldmatrix.sync.aligned.m8n8.x4.shared.b16 {%0,%1,%2,%3}, [%4];" \
        : "=r"((R)[0]), "=r"((R)[1]), "=r"((R)[2]), "=r"((R)[3]) : "r"(addr))

#define LDSM_X4T(R, addr) \
    asm volatile("ldmatrix.sync.aligned.m8n8.x4.trans.shared.b16 {%0,%1,%2,%3}, [%4];" \
        : "=r"((R)[0]), "=r"((R)[1]), "=r"((R)[2]), "=r"((R)[3]) : "r"(addr))

#define MMA16816(C, A, b0, b1) \
    asm volatile("mma.sync.aligned.m16n8k16.row.col.f32.bf16.bf16.f32 " \
        "{%0,%1,%2,%3},{%4,%5,%6,%7},{%8,%9},{%0,%1,%2,%3};" \
        : "+f"((C)[0]), "+f"((C)[1]), "+f"((C)[2]), "+f"((C)[3]) \
        : "r"((A)[0]), "r"((A)[1]), "r"((A)[2]), "r"((A)[3]), "r"(b0), "r"(b1))

#define CP16(dst, src) \
    asm volatile("cp.async.cg.shared.global [%0], [%1], 16;" :: "r"(dst), "l"(src))
#define CP_COMMIT() asm volatile("cp.async.commit_group;" ::: "memory")
#define CP_WAIT0()  asm volatile("cp.async.wait_group 0;" ::: "memory")

static __device__ __forceinline__ uint32_t smem_u32(const void* p) {
    return (uint32_t)__cvta_generic_to_shared(p);
}
static __device__ __forceinline__ float tanh_fast(float x) {
    float y; asm("tanh.approx.f32 %0, %1;" : "=f"(y) : "f"(x)); return y;
}
static __device__ __forceinline__ uint32_t packbf(float x, float y) {
    __nv_bfloat162 h = __float22bfloat162_rn(make_float2(x, y));
    return *(uint32_t*)&h;
}

// ---------------- setup1: wfold + Wle/G/biasc + pq split-K partials ----------------
__global__ __launch_bounds__(256)
void k_setup1(const float* __restrict__ Wm, const float* __restrict__ Wl,
              const float* __restrict__ We, const float* __restrict__ query,
              const float* __restrict__ Wq, const float* __restrict__ conv_w,
              const float* __restrict__ conv_b) {
    __shared__ float sh[8192];
    const int bid = blockIdx.x, tid = threadIdx.x;

    if (bid < 64) {
        const int r0 = bid * 8;
        float* w_sm = sh;
        #pragma unroll
        for (int r = 0; r < 8; ++r) w_sm[r * 256 + tid] = Wm[(size_t)(r0 + r) * Ux + tid];
        __syncthreads();
        float acc[8];
        #pragma unroll
        for (int r = 0; r < 8; ++r) acc[r] = 0.f;
        #pragma unroll 1
        for (int v0 = 0; v0 < Ux; v0 += 16) {
            float we[16];
            #pragma unroll
            for (int j = 0; j < 16; ++j) we[j] = We[(size_t)(v0 + j) * Ux + tid];
            #pragma unroll
            for (int j = 0; j < 16; ++j)
                #pragma unroll
                for (int r = 0; r < 8; ++r)
                    acc[r] = fmaf(w_sm[r * 256 + v0 + j], we[j], acc[r]);
        }
        #pragma unroll
        for (int r = 0; r < 8; ++r)
            g_Bw[(size_t)(r0 + r) * Ux + tid] = __float2bfloat16(acc[r]);
    } else if (bid == 64) {
        float* wl_sm = sh;               // [32][256]
        for (int i = tid; i < FILTx * Ux; i += 256) wl_sm[i] = Wl[i];
        __syncthreads();
        float acc[32];
        #pragma unroll
        for (int f = 0; f < 32; ++f) acc[f] = 0.f;
        #pragma unroll 1
        for (int v0 = 0; v0 < Ux; v0 += 8) {
            float we[8];
            #pragma unroll
            for (int j = 0; j < 8; ++j) we[j] = We[(size_t)(v0 + j) * Ux + tid];
            #pragma unroll
            for (int j = 0; j < 8; ++j)
                #pragma unroll
                for (int f = 0; f < 32; ++f)
                    acc[f] = fmaf(wl_sm[f * 256 + v0 + j], we[j], acc[f]);
        }
        __syncthreads();
        #pragma unroll
        for (int f = 0; f < 32; ++f) wl_sm[f * 256 + tid] = acc[f];   // now Wle
        __syncthreads();
        #pragma unroll 1
        for (int k = 0; k < KWx; ++k) {
            float g = 0.f;
            #pragma unroll
            for (int f = 0; f < 32; ++f) g = fmaf(conv_w[f * KWx + k], wl_sm[f * 256 + tid], g);
            g_Bw[(size_t)(ENCx + k) * Ux + tid] = __float2bfloat16(g);
        }
        g_Bw[(size_t)(KTOT - 1) * Ux + tid] = __float2bfloat16(0.f);  // pad row
        float bc = 0.f;
        #pragma unroll
        for (int f = 0; f < 32; ++f) bc = fmaf(conv_b[f], wl_sm[f * 256 + tid], bc);
        g_biasc[tid] = bc;
    } else {
        const int i = bid - 65;
        const int b0 = (i >> 2) * 4;
        const int h0 = (i & 3) * 256;
        float* q_sm = sh;                // [4][256]
        #pragma unroll
        for (int j = 0; j < 4; ++j) {
            int idx = j * 256 + tid;
            int bb = idx >> 8, h = idx & 255;
            q_sm[idx] = query[((size_t)(b0 + bb) * 2 + 1) * HIDx + h0 + h];
        }
        __syncthreads();
        float a[4];
        #pragma unroll
        for (int j = 0; j < 4; ++j) a[j] = 0.f;
        #pragma unroll 1
        for (int v0 = 0; v0 < 256; v0 += 16) {
            float wq[16];
            #pragma unroll
            for (int j = 0; j < 16; ++j) wq[j] = Wq[(size_t)(h0 + v0 + j) * Ux + tid];
            #pragma unroll
            for (int j = 0; j < 16; ++j)
                #pragma unroll
                for (int bb = 0; bb < 4; ++bb)
                    a[bb] = fmaf(q_sm[bb * 256 + v0 + j], wq[j], a[bb]);
        }
        #pragma unroll
        for (int bb = 0; bb < 4; ++bb)
            g_pqp[((size_t)(i & 3) * Bx + b0 + bb) * Ux + tid] = a[bb];
    }
}

// ---------------- setup2: combine pq partials, @We, + be ----------------
__global__ __launch_bounds__(256)
void k_setup2(const float* __restrict__ bq, const float* __restrict__ bl,
              const float* __restrict__ bm, const float* __restrict__ We,
              const float* __restrict__ be) {
    __shared__ float t_sm[4][256];
    const int b0 = blockIdx.x * 4, tid = threadIdx.x;
    float base = bq[tid] + bl[tid] + bm[tid];
    #pragma unroll
    for (int bb = 0; bb < 4; ++bb) {
        float t = base;
        #pragma unroll
        for (int s = 0; s < 4; ++s) t += g_pqp[((size_t)s * Bx + b0 + bb) * Ux + tid];
        t_sm[bb][tid] = t;
    }
    __syncthreads();
    float c[4];
    #pragma unroll
    for (int bb = 0; bb < 4; ++bb) c[bb] = be[tid];
    #pragma unroll 1
    for (int v0 = 0; v0 < Ux; v0 += 16) {
        float we[16];
        #pragma unroll
        for (int j = 0; j < 16; ++j) we[j] = We[(size_t)(v0 + j) * Ux + tid];
        #pragma unroll
        for (int j = 0; j < 16; ++j)
            #pragma unroll
            for (int bb = 0; bb < 4; ++bb)
                c[bb] = fmaf(t_sm[bb][v0 + j], we[j], c[bb]);
    }
    #pragma unroll
    for (int bb = 0; bb < 4; ++bb) g_pqe[(size_t)(b0 + bb) * Ux + tid] = c[bb];
}

// ---------------- alignment no-op (keeps k_main at launch #4 for ncu) ----------------
__global__ void k_noop() {}

// ---------------- main: BM=64, 256 threads (8 warps, 2m x 4n), warp = 32m x 64n ----------------
__global__ __launch_bounds__(256, 2)
void k_main(const float* __restrict__ memory, const float* __restrict__ state,
            const float* __restrict__ v_a) {
    extern __shared__ char smem[];
    const int b    = blockIdx.x >> 5;
    const int tile = blockIdx.x & 31;
    const int t0   = tile * BM;
    const int tid  = threadIdx.x;
    const int lane = tid & 31;
    const int warp = tid >> 5;
    const int wm   = warp >> 2;                 // 0..1 (32 rows each)
    const int wn   = warp & 3;                  // 0..3 (64 cols each)

    float* pq_sm = (float*)(smem + PQ_OFF);
    float* va_sm = (float*)(smem + VA_OFF);
    float* s_sm  = (float*)(smem + S_OFF);
    float* st_sm = (float*)(smem + ST_OFF);
    float* se    = (float*)(smem + SE_OFF);
    float* e_red = (float*)(smem + ER_OFF);     // [4][64]

    pq_sm[tid] = g_pqe[b * Ux + tid] + g_biasc[tid];
    va_sm[tid] = v_a[tid];
    if (tid < BM) st_sm[tid] = state[b * Tt + t0 + tid];
    if (tid < BM + 31) {
        int t = t0 + tid - 15;
        se[tid] = (t >= 0 && t < Tt) ? state[b * Tt + t] : 0.f;
    }

    const float* memb = memory + ((size_t)(b * Tt + t0)) * ENCx;
    const char*  bwp  = (const char*)g_Bw;
    const uint32_t smb = smem_u32(smem);

    // B copy: chunk c -> stage (16KB, 4 CP16/thread)
    auto copyB = [&](int c, int stage) {
        #pragma unroll
        for (int j = 0; j < 4; ++j) {
            int u = j * 256 + tid;               // 1024 16B units (32 rows x 32)
            int row = u >> 5, c16 = u & 31;
            uint32_t dst = smb + BST_OFF + stage * BST_STRIDE + row * 528 + c16 * 16;
            const char* src = bwp + (size_t)(c * 32 + row) * 512 + c16 * 16;
            CP16(dst, src);
        }
    };

    __syncthreads();                             // se/st/pq visible

    copyB(0, 0); CP_COMMIT();

    // A prefetch: 2 float4 per thread cover the 64x32 chunk
    const int ar0 = tid >> 2, ac0 = tid & 3;     // u = tid: row tid>>3? use uniform formula
    float4 aReg[2];
    #pragma unroll
    for (int j = 0; j < 2; ++j) {
        int u = j * 256 + tid, row = u >> 3, c4 = u & 7;
        aReg[j] = *(const float4*)&memb[(size_t)row * ENCx + c4 * 4];
    }

    float acc[16][4];
    #pragma unroll
    for (int i = 0; i < 16; ++i) { acc[i][0]=0.f; acc[i][1]=0.f; acc[i][2]=0.f; acc[i][3]=0.f; }

    // hoisted lane-constant LDSM offsets
    const uint32_t a_lane = (uint32_t)(lane & 15) * 80 + ((lane >> 4) << 4);
    const uint32_t b_lane = (uint32_t)(lane & 15) * 528 + (((lane >> 4) << 3) << 1);

    #pragma unroll 1
    for (int c = 0; c < NCH; ++c) {
        const int stage = c & 1;
        char* Ab = smem + ABUF_OFF + stage * ABUF_STRIDE;

        // 1. store A chunk c (bf16)
        if (c < 16) {
            #pragma unroll
            for (int j = 0; j < 2; ++j) {
                int u = j * 256 + tid, row = u >> 3, c4 = u & 7;
                uint2 pk;
                pk.x = packbf(aReg[j].x, aReg[j].y);
                pk.y = packbf(aReg[j].z, aReg[j].w);
                *(uint2*)(Ab + row * 80 + c4 * 8) = pk;
            }
        } else {
            #pragma unroll
            for (int j = 0; j < 2; ++j) {
                int u = j * 256 + tid, row = u >> 3, c4 = u & 7;
                float v[4];
                #pragma unroll
                for (int e = 0; e < 4; ++e) {
                    int k = c4 * 4 + e;
                    v[e] = (k < KWx) ? se[row + k] : 0.f;
                }
                uint2 pk;
                pk.x = packbf(v[0], v[1]);
                pk.y = packbf(v[2], v[3]);
                *(uint2*)(Ab + row * 80 + c4 * 8) = pk;
            }
        }

        // 2. wait B chunk c
        CP_WAIT0();
        __syncthreads();

        // 3. prefetch A chunk c+1; issue B copy c+1
        if (c + 1 < 16) {
            #pragma unroll
            for (int j = 0; j < 2; ++j) {
                int u = j * 256 + tid, row = u >> 3, c4 = u & 7;
                aReg[j] = *(const float4*)&memb[(size_t)row * ENCx + (c + 1) * 32 + c4 * 4];
            }
        }
        if (c + 1 < NCH) copyB(c + 1, (c + 1) & 1);
        CP_COMMIT();

        // 4. compute chunk c (warp tile 32x64)
        const uint32_t abase = smb + ABUF_OFF + stage * ABUF_STRIDE + (uint32_t)(wm * 32) * 80;
        const uint32_t bst   = smb + BST_OFF + stage * BST_STRIDE + (uint32_t)(wn * 64) * 2;

        #pragma unroll
        for (int ks = 0; ks < 2; ++ks) {
            uint32_t a0[4], a1[4];
            LDSM_X4(a0, abase + a_lane + ks * 32);
            LDSM_X4(a1, abase + 16 * 80 + a_lane + ks * 32);
            #pragma unroll
            for (int p = 0; p < 4; ++p) {
                uint32_t bf[4];
                LDSM_X4T(bf, bst + b_lane + (uint32_t)(ks * 16) * 528 + p * 32);
                MMA16816(acc[2 * p],         a0, bf[0], bf[1]);
                MMA16816(acc[2 * p + 1],     a0, bf[2], bf[3]);
                MMA16816(acc[8 + 2 * p],     a1, bf[0], bf[1]);
                MMA16816(acc[8 + 2 * p + 1], a1, bf[2], bf[3]);
            }
        }
        __syncthreads();                         // gates stage/Ab reuse
    }

    // ---- epilogue: tanh (MUFU), v_a dot, per-row energy reduce ----
    #pragma unroll
    for (int mt = 0; mt < 2; ++mt) {
        float e0 = 0.f, e1 = 0.f;
        #pragma unroll
        for (int nt = 0; nt < 8; ++nt) {
            const float* cc = acc[mt * 8 + nt];
            int u0 = wn * 64 + nt * 8 + (lane & 3) * 2;
            e0 = fmaf(va_sm[u0],     tanh_fast(cc[0] + pq_sm[u0]),     e0);
            e0 = fmaf(va_sm[u0 + 1], tanh_fast(cc[1] + pq_sm[u0 + 1]), e0);
            e1 = fmaf(va_sm[u0],     tanh_fast(cc[2] + pq_sm[u0]),     e1);
            e1 = fmaf(va_sm[u0 + 1], tanh_fast(cc[3] + pq_sm[u0 + 1]), e1);
        }
        e0 += __shfl_xor_sync(0xffffffffu, e0, 1);
        e0 += __shfl_xor_sync(0xffffffffu, e0, 2);
        e1 += __shfl_xor_sync(0xffffffffu, e1, 1);
        e1 += __shfl_xor_sync(0xffffffffu, e1, 2);
        if ((lane & 3) == 0) {
            int row = wm * 32 + mt * 16 + (lane >> 2);
            e_red[wn * 64 + row]     = e0;
            e_red[wn * 64 + row + 8] = e1;
        }
    }
    __syncthreads();
    if (tid < BM) {
        float E = e_red[tid] + e_red[64 + tid] + e_red[128 + tid] + e_red[192 + tid];
        s_sm[tid] = 1.f / (1.f + __expf(-E));
    }
    __syncthreads();

    if (tid < 32) {
        float S  = s_sm[tid]  + s_sm[tid + 32];
        float St = st_sm[tid] + st_sm[tid + 32];
        #pragma unroll
        for (int off = 16; off > 0; off >>= 1) {
            S  += __shfl_xor_sync(0xffffffffu, S, off);
            St += __shfl_xor_sync(0xffffffffu, St, off);
        }
        if (tid == 0) {
            g_pS[b * NTILES + tile]  = S;
            g_pSt[b * NTILES + tile] = St;
        }
    }

    // ---- weighted memory column sums: 2 columns per thread ----
    float aA0 = 0.f, aB0 = 0.f, aA1 = 0.f, aB1 = 0.f;
    const float* p0 = memb + tid;
    const float* p1 = memb + tid + 256;
    #pragma unroll 8
    for (int m = 0; m < BM; ++m) {
        float v0 = p0[(size_t)m * ENCx];
        float v1 = p1[(size_t)m * ENCx];
        float sw = s_sm[m], stw = st_sm[m];
        aA0 = fmaf(stw, v0, aA0);  aB0 = fmaf(sw, v0, aB0);
        aA1 = fmaf(stw, v1, aA1);  aB1 = fmaf(sw, v1, aB1);
    }
    size_t base = (size_t)(b * NTILES + tile) * ENCx;
    g_pA[base + tid]       = aA0;
    g_pA[base + tid + 256] = aA1;
    g_pB[base + tid]       = aB0;
    g_pB[base + tid + 256] = aB1;
}

// ---------------- finalize: 1024 threads, e-split GEMM ----------------
__global__ __launch_bounds__(1024)
void k_final(const float* __restrict__ Wm, const float* __restrict__ bm,
             float* __restrict__ out) {
    __shared__ float M[ENCx];
    __shared__ float sS[2];
    __shared__ float part[3][Ux];
    const int b = blockIdx.x, tid = threadIdx.x;   // 1024 threads
    const int q = tid >> 8, u = tid & 255;

    if (tid < 32) {
        float S  = g_pS[b * NTILES + tid];
        float St = g_pSt[b * NTILES + tid];
        #pragma unroll
        for (int off = 16; off > 0; off >>= 1) {
            S  += __shfl_xor_sync(0xffffffffu, S, off);
            St += __shfl_xor_sync(0xffffffffu, St, off);
        }
        if (tid == 0) { sS[0] = S; sS[1] = St; }
    }

    float a = 0.f, bb = 0.f;
    if (tid < ENCx) {
        #pragma unroll
        for (int t = 0; t < NTILES; ++t) {
            a  += g_pA[(size_t)(b * NTILES + t) * ENCx + tid];
            bb += g_pB[(size_t)(b * NTILES + t) * ENCx + tid];
        }
    }
    __syncthreads();
    if (tid < ENCx) M[tid] = a + bb * (1.f / sS[0]);
    __syncthreads();

    float acc = 0.f;
    #pragma unroll 1
    for (int e0 = q * 128; e0 < q * 128 + 128; e0 += 8) {
        float wv[8];
        #pragma unroll
        for (int j = 0; j < 8; ++j) wv[j] = Wm[(size_t)(e0 + j) * Ux + u];
        #pragma unroll
        for (int j = 0; j < 8; ++j) acc = fmaf(M[e0 + j], wv[j], acc);
    }
    if (q > 0) part[q - 1][u] = acc;
    __syncthreads();
    if (q == 0) {
        float cumsum = sS[1] + 1.f;
        out[b * Ux + u] = fmaf(cumsum, bm[u],
                               acc + part[0][u] + part[1][u] + part[2][u]);
    }
}

// ---------------- launch ----------------
extern "C" void kernel_launch(void* const* d_in, const int* in_sizes, int n_in,
                              void* d_out, int out_size) {
    const float* query  = (const float*)d_in[0];
    const float* state  = (const float*)d_in[1];
    const float* memory = (const float*)d_in[2];
    const float* Wq     = (const float*)d_in[3];
    const float* bq     = (const float*)d_in[4];
    const float* Wm     = (const float*)d_in[5];
    const float* bm     = (const float*)d_in[6];
    const float* Wl     = (const float*)d_in[7];
    const float* bl     = (const float*)d_in[8];
    const float* conv_w = (const float*)d_in[9];
    const float* conv_b = (const float*)d_in[10];
    const float* We     = (const float*)d_in[11];
    const float* be     = (const float*)d_in[12];
    const float* v_a    = (const float*)d_in[13];
    float* out = (float*)d_out;

    cudaFuncSetAttribute(k_main, cudaFuncAttributeMaxDynamicSharedMemorySize, SM_TOTAL);

    k_setup1<<<129, 256>>>(Wm, Wl, We, query, Wq, conv_w, conv_b);
    k_setup2<<<16, 256>>>(bq, bl, bm, We, be);
    k_noop<<<1, 32>>>();                                   // aligns k_main to launch #4 for ncu
    k_main<<<Bx * NTILES, 256, SM_TOTAL>>>(memory, state, v_a);
    k_final<<<Bx, 1024>>>(Wm, bm, out);
}